// round 11
// baseline (speedup 1.0000x reference)
#include <cuda_runtime.h>
#include <cstdint>

#define N_FEATURES 16
#define N_CLASSES 10
#define N_INTERNAL 1023
#define BLOCK 512
#define GRID 608   // 4 CTAs/SM x 152 SMs
#define N_RECORDS 511

// Dynamic smem layout (bytes):
//   [0,     8192)  float4 rec[512]      2-level records {thr_i, thr_L, thr_R, feats}
//   [8192, 40960)  float xs[16][512]    transposed per-thread features (bank tid%32)
#define SMEM_BYTES 40960

__global__ __launch_bounds__(BLOCK, 4)
void dtree_kernel(const float* __restrict__ X,
                  const int* __restrict__ tfeat,
                  const float* __restrict__ tthr,
                  const float* __restrict__ tval,
                  float* __restrict__ out,
                  int n)
{
    extern __shared__ char smem_raw[];
    float4* rec_s = reinterpret_cast<float4*>(smem_raw);
    float*  xs    = reinterpret_cast<float*>(smem_raw + 8192);

    const int tid = threadIdx.x;

    // 2-level records for even-level nodes i (levels 0,2,4,6,8 -> i < 511).
    // feats packed: fI | fL<<4 | fR<<8.
    for (int i = tid; i < N_RECORDS; i += BLOCK) {
        int fI = tfeat[i];
        int fL = tfeat[2 * i + 1];
        int fR = tfeat[2 * i + 2];
        rec_s[i] = make_float4(tthr[i], tthr[2 * i + 1], tthr[2 * i + 2],
                               __int_as_float(fI | (fL << 4) | (fR << 8)));
    }
    __syncthreads();

    // Levels 0-1 record is identical for every sample: registers.
    const float4 rc0 = rec_s[0];
    const int    fp0 = __float_as_int(rc0.w);

    const int lane   = tid & 31;
    const int stride = gridDim.x * BLOCK;
    const float2* __restrict__ tv2 = reinterpret_cast<const float2*>(tval);

    for (int i = blockIdx.x * BLOCK + tid; i < n; i += stride) {
        // Stage 16 features into own smem column (bank tid%32 for every feature
        // index -> all dynamic feature reads below are conflict-free LDS.32).
        // No sync needed: only this thread touches column tid.
        const float4* __restrict__ xr = reinterpret_cast<const float4*>(X + (size_t)i * N_FEATURES);
        float4 a = xr[0], b = xr[1], c = xr[2], d = xr[3];
        xs[ 0*BLOCK+tid]=a.x; xs[ 1*BLOCK+tid]=a.y; xs[ 2*BLOCK+tid]=a.z; xs[ 3*BLOCK+tid]=a.w;
        xs[ 4*BLOCK+tid]=b.x; xs[ 5*BLOCK+tid]=b.y; xs[ 6*BLOCK+tid]=b.z; xs[ 7*BLOCK+tid]=b.w;
        xs[ 8*BLOCK+tid]=c.x; xs[ 9*BLOCK+tid]=c.y; xs[10*BLOCK+tid]=c.z; xs[11*BLOCK+tid]=c.w;
        xs[12*BLOCK+tid]=d.x; xs[13*BLOCK+tid]=d.y; xs[14*BLOCK+tid]=d.z; xs[15*BLOCK+tid]=d.w;

        int node = 0;
        #pragma unroll
        for (int pair = 0; pair < 5; ++pair) {
            float4 rc;
            int fp;
            if (pair == 0) { rc = rc0; fp = fp0; }
            else           { rc = rec_s[node]; fp = __float_as_int(rc.w); }

            const int f0 = fp & 15;
            const float xv0 = xs[(f0 << 9) + tid];          // conflict-free LDS.32
            const bool c0 = (xv0 > rc.x);

            const int   f1   = (c0 ? (fp >> 8) : (fp >> 4)) & 15;
            const float thr1 = c0 ? rc.z : rc.y;
            const float xv1 = xs[(f1 << 9) + tid];          // conflict-free LDS.32
            const bool c1 = (xv1 > thr1);

            node = 4 * node + 3 + (c0 ? 2 : 0) + (c1 ? 1 : 0);
        }

        // Leaf row base (float2 units) into GLOBAL tval — L1/L2-resident (80 KB).
        const int myoff = node * (N_CLASSES / 2);

        // Warp-cooperative: gather rows from cache, write fully-coalesced.
        float2* __restrict__ orow =
            reinterpret_cast<float2*>(out) + (size_t)(i - lane) * (N_CLASSES / 2);
        #pragma unroll
        for (int k = 0; k < 5; ++k) {
            int e  = k * 32 + lane;      // 0..159
            int s  = e / 5;              // sample within warp batch
            int cc = e - s * 5;          // float2 index within row
            int off = __shfl_sync(0xffffffffu, myoff, s);
            orow[e] = __ldg(&tv2[off + cc]);
        }
    }
}

extern "C" void kernel_launch(void* const* d_in, const int* in_sizes, int n_in,
                              void* d_out, int out_size)
{
    const float* X     = (const float*)d_in[0];
    const int*   tfeat = (const int*)  d_in[1];
    const float* tthr  = (const float*)d_in[2];
    // d_in[3]/d_in[4] (left/right): implicit complete binary tree
    const float* tval  = (const float*)d_in[5];
    // d_in[6] (is_leaf): redundant at depth 10

    float* out = (float*)d_out;
    int n = in_sizes[0] / N_FEATURES;

    static bool attr_set = false;
    if (!attr_set) {
        cudaFuncSetAttribute(dtree_kernel,
                             cudaFuncAttributeMaxDynamicSharedMemorySize, SMEM_BYTES);
        attr_set = true;
    }

    int blocks = (n + BLOCK - 1) / BLOCK;
    if (blocks > GRID) blocks = GRID;

    dtree_kernel<<<blocks, BLOCK, SMEM_BYTES>>>(X, tfeat, tthr, tval, out, n);
}

// round 12
// speedup vs baseline: 1.1098x; 1.1098x over previous
#include <cuda_runtime.h>
#include <cstdint>

#define N_FEATURES 16
#define N_CLASSES 10
#define N_INTERNAL 1023
#define N_LEAVES 1024
#define BLOCK 512
#define GRID 456   // 3 CTAs/SM x 152 SMs
#define N_RECORDS 511

// Dynamic smem: float4 rec[512] only (8 KB)
#define SMEM_BYTES 8192

// 64B-stride padded leaf table: row r holds tval[(1023+r)*10 .. +10), rest pad.
// Each row sits entirely within one 64B half-line -> minimal gather wavefronts.
__device__ float2 g_lv_pad[N_LEAVES * 8];   // 64 KB scratch (static, no alloc)

__global__ void pad_leaf_kernel(const float* __restrict__ tval)
{
    int r = blockIdx.x * blockDim.x + threadIdx.x;
    if (r < N_LEAVES) {
        const float2* __restrict__ src =
            reinterpret_cast<const float2*>(tval + (size_t)(N_INTERNAL + r) * N_CLASSES);
        #pragma unroll
        for (int c = 0; c < 5; ++c)
            g_lv_pad[r * 8 + c] = src[c];
    }
}

__global__ __launch_bounds__(BLOCK, 3)
void dtree_kernel(const float* __restrict__ X,
                  const int* __restrict__ tfeat,
                  const float* __restrict__ tthr,
                  float* __restrict__ out,
                  int n)
{
    extern __shared__ char smem_raw[];
    float4* rec_s = reinterpret_cast<float4*>(smem_raw);

    const int tid = threadIdx.x;

    // 2-level records for even-level nodes i (levels 0,2,4,6,8 -> i < 511).
    // feats packed: fI | fL<<4 | fR<<8.
    for (int i = tid; i < N_RECORDS; i += BLOCK) {
        int fI = tfeat[i];
        int fL = tfeat[2 * i + 1];
        int fR = tfeat[2 * i + 2];
        rec_s[i] = make_float4(tthr[i], tthr[2 * i + 1], tthr[2 * i + 2],
                               __int_as_float(fI | (fL << 4) | (fR << 8)));
    }
    __syncthreads();

    // Levels 0-1 record is identical for every sample: registers.
    const float4 rc0 = rec_s[0];
    const int    fp0 = __float_as_int(rc0.w);

    const int lane   = tid & 31;
    const int stride = gridDim.x * BLOCK;

    for (int i = blockIdx.x * BLOCK + tid; i < n; i += stride) {
        const float4* __restrict__ xr = reinterpret_cast<const float4*>(X + (size_t)i * N_FEATURES);
        float4 a = xr[0], b = xr[1], c = xr[2], d = xr[3];

        int node = 0;
        #pragma unroll
        for (int pair = 0; pair < 5; ++pair) {
            float4 rc;
            int fp;
            if (pair == 0) { rc = rc0; fp = fp0; }          // register-resident
            else           { rc = rec_s[node]; fp = __float_as_int(rc.w); }

            const int f0 = fp & 15;
            float s0 = (f0 & 1) ? a.y : a.x;  float s1 = (f0 & 1) ? a.w : a.z;
            float s2 = (f0 & 1) ? b.y : b.x;  float s3 = (f0 & 1) ? b.w : b.z;
            float s4 = (f0 & 1) ? c.y : c.x;  float s5 = (f0 & 1) ? c.w : c.z;
            float s6 = (f0 & 1) ? d.y : d.x;  float s7 = (f0 & 1) ? d.w : d.z;
            float t0 = (f0 & 2) ? s1 : s0;    float t1 = (f0 & 2) ? s3 : s2;
            float t2 = (f0 & 2) ? s5 : s4;    float t3 = (f0 & 2) ? s7 : s6;
            float u0 = (f0 & 4) ? t1 : t0;    float u1 = (f0 & 4) ? t3 : t2;
            float xv0 = (f0 & 8) ? u1 : u0;
            const bool c0 = (xv0 > rc.x);

            const int   f1   = (c0 ? (fp >> 8) : (fp >> 4)) & 15;
            const float thr1 = c0 ? rc.z : rc.y;
            float v0 = (f1 & 1) ? a.y : a.x;  float v1 = (f1 & 1) ? a.w : a.z;
            float v2 = (f1 & 1) ? b.y : b.x;  float v3 = (f1 & 1) ? b.w : b.z;
            float v4 = (f1 & 1) ? c.y : c.x;  float v5 = (f1 & 1) ? c.w : c.z;
            float v6 = (f1 & 1) ? d.y : d.x;  float v7 = (f1 & 1) ? d.w : d.z;
            float w0 = (f1 & 2) ? v1 : v0;    float w1 = (f1 & 2) ? v3 : v2;
            float w2 = (f1 & 2) ? v5 : v4;    float w3 = (f1 & 2) ? v7 : v6;
            float y0 = (f1 & 4) ? w1 : w0;    float y1 = (f1 & 4) ? w3 : w2;
            float xv1 = (f1 & 8) ? y1 : y0;
            const bool c1 = (xv1 > thr1);

            node = 4 * node + 3 + (c0 ? 2 : 0) + (c1 ? 1 : 0);
        }

        // Leaf row base in padded table (float2 units, stride 8 = 64B rows).
        const int myoff = (node - N_INTERNAL) * 8;

        // Warp-cooperative: gather 64B-aligned rows from L1/L2, write coalesced.
        float2* __restrict__ orow =
            reinterpret_cast<float2*>(out) + (size_t)(i - lane) * (N_CLASSES / 2);
        #pragma unroll
        for (int k = 0; k < 5; ++k) {
            int e  = k * 32 + lane;      // 0..159
            int s  = e / 5;              // sample within warp batch
            int cc = e - s * 5;          // float2 index within row
            int off = __shfl_sync(0xffffffffu, myoff, s);
            orow[e] = __ldg(&g_lv_pad[off + cc]);
        }
    }
}

extern "C" void kernel_launch(void* const* d_in, const int* in_sizes, int n_in,
                              void* d_out, int out_size)
{
    const float* X     = (const float*)d_in[0];
    const int*   tfeat = (const int*)  d_in[1];
    const float* tthr  = (const float*)d_in[2];
    // d_in[3]/d_in[4] (left/right): implicit complete binary tree
    const float* tval  = (const float*)d_in[5];
    // d_in[6] (is_leaf): redundant at depth 10

    float* out = (float*)d_out;
    int n = in_sizes[0] / N_FEATURES;

    static bool attr_set = false;
    if (!attr_set) {
        cudaFuncSetAttribute(dtree_kernel,
                             cudaFuncAttributeMaxDynamicSharedMemorySize, SMEM_BYTES);
        attr_set = true;
    }

    // 1) Repack leaf rows to 64B stride (tiny; graph-capturable kernel launch).
    pad_leaf_kernel<<<2, 512>>>(tval);

    // 2) Main traversal kernel.
    int blocks = (n + BLOCK - 1) / BLOCK;
    if (blocks > GRID) blocks = GRID;
    dtree_kernel<<<blocks, BLOCK, SMEM_BYTES>>>(X, tfeat, tthr, out, n);
}

// round 13
// speedup vs baseline: 1.1172x; 1.0067x over previous
#include <cuda_runtime.h>
#include <cstdint>

#define N_FEATURES 16
#define N_CLASSES 10
#define N_INTERNAL 1023
#define BLOCK 512
#define GRID 456   // 3 CTAs/SM x 152 SMs
#define N_RECORDS 511

// Dynamic smem: float4 rec[512] only (8 KB)
#define SMEM_BYTES 8192

__global__ __launch_bounds__(BLOCK, 3)
void dtree_kernel(const float* __restrict__ X,
                  const int* __restrict__ tfeat,
                  const float* __restrict__ tthr,
                  const float* __restrict__ tval,
                  float* __restrict__ out,
                  int n)
{
    extern __shared__ char smem_raw[];
    float4* rec_s = reinterpret_cast<float4*>(smem_raw);

    const int tid = threadIdx.x;

    // 2-level records for even-level nodes i (levels 0,2,4,6,8 -> i < 511).
    // feats packed: fI | fL<<4 | fR<<8.
    for (int i = tid; i < N_RECORDS; i += BLOCK) {
        int fI = tfeat[i];
        int fL = tfeat[2 * i + 1];
        int fR = tfeat[2 * i + 2];
        rec_s[i] = make_float4(tthr[i], tthr[2 * i + 1], tthr[2 * i + 2],
                               __int_as_float(fI | (fL << 4) | (fR << 8)));
    }
    __syncthreads();

    // Levels 0-1 record is identical for every sample: registers.
    const float4 rc0 = rec_s[0];
    const int    fp0 = __float_as_int(rc0.w);

    const int lane   = tid & 31;
    const int stride = gridDim.x * BLOCK;
    const float2* __restrict__ tv2 = reinterpret_cast<const float2*>(tval);

    for (int i = blockIdx.x * BLOCK + tid; i < n; i += stride) {
        // X is read-once: streaming loads keep the leaf table L1-resident.
        const float4* __restrict__ xr = reinterpret_cast<const float4*>(X + (size_t)i * N_FEATURES);
        float4 a = __ldcs(xr + 0);
        float4 b = __ldcs(xr + 1);
        float4 c = __ldcs(xr + 2);
        float4 d = __ldcs(xr + 3);

        int node = 0;
        #pragma unroll
        for (int pair = 0; pair < 5; ++pair) {
            float4 rc;
            int fp;
            if (pair == 0) { rc = rc0; fp = fp0; }          // register-resident
            else           { rc = rec_s[node]; fp = __float_as_int(rc.w); }

            const int f0 = fp & 15;
            float s0 = (f0 & 1) ? a.y : a.x;  float s1 = (f0 & 1) ? a.w : a.z;
            float s2 = (f0 & 1) ? b.y : b.x;  float s3 = (f0 & 1) ? b.w : b.z;
            float s4 = (f0 & 1) ? c.y : c.x;  float s5 = (f0 & 1) ? c.w : c.z;
            float s6 = (f0 & 1) ? d.y : d.x;  float s7 = (f0 & 1) ? d.w : d.z;
            float t0 = (f0 & 2) ? s1 : s0;    float t1 = (f0 & 2) ? s3 : s2;
            float t2 = (f0 & 2) ? s5 : s4;    float t3 = (f0 & 2) ? s7 : s6;
            float u0 = (f0 & 4) ? t1 : t0;    float u1 = (f0 & 4) ? t3 : t2;
            float xv0 = (f0 & 8) ? u1 : u0;
            const bool c0 = (xv0 > rc.x);

            const int   f1   = (c0 ? (fp >> 8) : (fp >> 4)) & 15;
            const float thr1 = c0 ? rc.z : rc.y;
            float v0 = (f1 & 1) ? a.y : a.x;  float v1 = (f1 & 1) ? a.w : a.z;
            float v2 = (f1 & 1) ? b.y : b.x;  float v3 = (f1 & 1) ? b.w : b.z;
            float v4 = (f1 & 1) ? c.y : c.x;  float v5 = (f1 & 1) ? c.w : c.z;
            float v6 = (f1 & 1) ? d.y : d.x;  float v7 = (f1 & 1) ? d.w : d.z;
            float w0 = (f1 & 2) ? v1 : v0;    float w1 = (f1 & 2) ? v3 : v2;
            float w2 = (f1 & 2) ? v5 : v4;    float w3 = (f1 & 2) ? v7 : v6;
            float y0 = (f1 & 4) ? w1 : w0;    float y1 = (f1 & 4) ? w3 : w2;
            float xv1 = (f1 & 8) ? y1 : y0;
            const bool c1 = (xv1 > thr1);

            node = 4 * node + 3 + (c0 ? 2 : 0) + (c1 ? 1 : 0);
        }

        // Leaf row base (float2 units into global tval; node includes +1023).
        const int myoff = node * (N_CLASSES / 2);

        // Warp-cooperative epilogue, wide stores:
        // warp block = 1280B contiguous = 80 float4; write 2x STG.128 + 1x STG.64
        // (issue cost ~32 cyc vs ~39 for 5x STG.64). Gathers stay 5x LDG.64.
        const int w0i = i - lane;  // warp-uniform base sample
        float4* __restrict__ ov4 = reinterpret_cast<float4*>(out + (size_t)w0i * N_CLASSES);
        float2* __restrict__ ov2 = reinterpret_cast<float2*>(out + (size_t)w0i * N_CLASSES);

        #pragma unroll
        for (int k = 0; k < 2; ++k) {
            int e4 = k * 32 + lane;          // float4 index 0..63
            int p0 = 2 * e4;                 // float2 index (even)
            int p1 = p0 + 1;                 // float2 index (odd)
            int s0i = p0 / 5, cc0 = p0 - s0i * 5;
            int s1i = p1 / 5, cc1 = p1 - s1i * 5;
            int off0 = __shfl_sync(0xffffffffu, myoff, s0i);
            int off1 = __shfl_sync(0xffffffffu, myoff, s1i);
            float2 lo = __ldg(&tv2[off0 + cc0]);
            float2 hi = __ldg(&tv2[off1 + cc1]);
            __stcs(&ov4[e4], make_float4(lo.x, lo.y, hi.x, hi.y));
        }
        {
            int p  = 128 + lane;             // float2 index 128..159
            int si = p / 5, cc = p - si * 5;
            int off = __shfl_sync(0xffffffffu, myoff, si);
            __stcs(&ov2[p], __ldg(&tv2[off + cc]));
        }
    }
}

extern "C" void kernel_launch(void* const* d_in, const int* in_sizes, int n_in,
                              void* d_out, int out_size)
{
    const float* X     = (const float*)d_in[0];
    const int*   tfeat = (const int*)  d_in[1];
    const float* tthr  = (const float*)d_in[2];
    // d_in[3]/d_in[4] (left/right): implicit complete binary tree
    const float* tval  = (const float*)d_in[5];
    // d_in[6] (is_leaf): redundant at depth 10

    float* out = (float*)d_out;
    int n = in_sizes[0] / N_FEATURES;

    static bool attr_set = false;
    if (!attr_set) {
        cudaFuncSetAttribute(dtree_kernel,
                             cudaFuncAttributeMaxDynamicSharedMemorySize, SMEM_BYTES);
        attr_set = true;
    }

    int blocks = (n + BLOCK - 1) / BLOCK;
    if (blocks > GRID) blocks = GRID;

    dtree_kernel<<<blocks, BLOCK, SMEM_BYTES>>>(X, tfeat, tthr, tval, out, n);
}